// round 10
// baseline (speedup 1.0000x reference)
#include <cuda_runtime.h>
#include <cstdint>

#define ROWS_TOTAL 32768
#define DIM 768
#define NF 16
#define NQ 8

#define BLOCK 128                    /* 4 warps */
#define RPT 4                        /* rows per thread (per warp: 32 lanes x 4) */
#define ROWS_PB 128
#define KQ 192                       /* K quarter per warp */
#define KB 8                         /* k per chunk per warp */
#define NCHUNK (KQ / KB)             /* 24 */
#define LDXS 36                      /* x_s row stride: 4*KB + 4 pad */
#define LDP 20                       /* partial row stride (conflict-free) */
#define W_FLOATS (DIM * NF)          /* 12288 = 48KB */
#define XBUF_FLOATS (ROWS_PB * LDXS) /* 4608 */
#define PART_FLOATS (4 * ROWS_PB * LDP) /* 10240 = 40KB, overlays x bufs */
#define SMEM_FLOATS (W_FLOATS + (PART_FLOATS > 2*XBUF_FLOATS ? PART_FLOATS : 2*XBUF_FLOATS))
#define SMEM_BYTES (SMEM_FLOATS * 4) /* 90112 -> 2 blocks/SM */

__device__ __forceinline__ void ffma2(unsigned long long &d,
                                      unsigned long long a,
                                      unsigned long long b) {
    asm("fma.rn.f32x2 %0, %1, %2, %0;" : "+l"(d) : "l"(a), "l"(b));
}

__device__ __forceinline__ unsigned long long splat(float v) {
    unsigned long long r;
    asm("mov.b64 %0, {%1, %1};" : "=l"(r) : "f"(v));
    return r;
}

__device__ __forceinline__ void cp_async16(float* dst, const float* src) {
    unsigned int d = (unsigned int)__cvta_generic_to_shared(dst);
    asm volatile("cp.async.cg.shared.global [%0], [%1], 16;" :: "r"(d), "l"(src));
}

/* stage chunk c: for every row, 4 quarter-segments of 8 floats (32B).
   1024 x 16B transfers, 8 per thread. dst layout: x_s[row*36 + q*8 + kk] */
__device__ __forceinline__ void stage_x(const float* __restrict__ xb,
                                        float* __restrict__ dst,
                                        int c, int tid) {
    #pragma unroll
    for (int t = 0; t < 8; t++) {
        int idx = t * BLOCK + tid;
        int h = idx & 1, q = (idx >> 1) & 3, row = idx >> 3;
        cp_async16(dst + row * LDXS + q * KB + h * 4,
                   xb + (size_t)row * DIM + q * KQ + c * KB + h * 4);
    }
    asm volatile("cp.async.commit_group;");
}

__global__ __launch_bounds__(BLOCK)
void qadapter_fused(const float* __restrict__ x,
                    const float* __restrict__ W,
                    const float* __restrict__ b,
                    const float* __restrict__ enc,
                    float* __restrict__ out) {
    extern __shared__ float smem[];
    float* W_s  = smem;                       /* 12288 floats */
    float* x_s  = smem + W_FLOATS;            /* 2 x 4608 floats */
    float* p_s  = smem + W_FLOATS;            /* 10240 floats, reused after loop */

    const int tid  = threadIdx.x;
    const int w    = tid >> 5;                /* warp id = k quarter */
    const int l    = tid & 31;                /* lane = base row */
    const int base = blockIdx.x * ROWS_PB;
    const float* xb = x + (size_t)base * DIM;

    /* ---- stage full W : group 0 (3072 float4 / 128 thr = 24 each) ---- */
    {
        const float4* Wsrc = reinterpret_cast<const float4*>(W);
        #pragma unroll
        for (int i = 0; i < 24; i++) {
            int g4 = i * BLOCK + tid;
            cp_async16(W_s + g4 * 4, reinterpret_cast<const float*>(Wsrc + g4));
        }
        asm volatile("cp.async.commit_group;");
    }
    stage_x(xb, x_s, 0, tid);                 /* group 1 */
    stage_x(xb, x_s + XBUF_FLOATS, 1, tid);   /* group 2 */

    unsigned long long acc[RPT][8];
    #pragma unroll
    for (int j = 0; j < RPT; j++)
        #pragma unroll
        for (int i = 0; i < 8; i++) acc[j][i] = 0ull;

    for (int ch = 0; ch < NCHUNK; ch++) {
        if (ch < NCHUNK - 1) asm volatile("cp.async.wait_group 1;");
        else                 asm volatile("cp.async.wait_group 0;");
        __syncthreads();

        const float* xr = x_s + (ch & 1) * XBUF_FLOATS + l * LDXS + w * KB;
        const float* wc = W_s + (w * KQ + ch * KB) * NF;

        #pragma unroll
        for (int kk = 0; kk < KB; kk += 4) {
            float4 xv[RPT];
            #pragma unroll
            for (int j = 0; j < RPT; j++)
                xv[j] = *reinterpret_cast<const float4*>(
                    xr + j * (32 * LDXS) + kk);
            const float xe[RPT][4] = {
                {xv[0].x, xv[0].y, xv[0].z, xv[0].w},
                {xv[1].x, xv[1].y, xv[1].z, xv[1].w},
                {xv[2].x, xv[2].y, xv[2].z, xv[2].w},
                {xv[3].x, xv[3].y, xv[3].z, xv[3].w}};
            #pragma unroll
            for (int kj = 0; kj < 4; kj++) {
                const ulonglong2* wp = reinterpret_cast<const ulonglong2*>(
                    wc + (kk + kj) * NF);
                ulonglong2 w01 = wp[0];   /* full-warp broadcast LDS.128 */
                ulonglong2 w23 = wp[1];
                ulonglong2 w45 = wp[2];
                ulonglong2 w67 = wp[3];
                #pragma unroll
                for (int j = 0; j < RPT; j++) {
                    unsigned long long xs = splat(xe[j][kj]);
                    ffma2(acc[j][0], xs, w01.x);
                    ffma2(acc[j][1], xs, w01.y);
                    ffma2(acc[j][2], xs, w23.x);
                    ffma2(acc[j][3], xs, w23.y);
                    ffma2(acc[j][4], xs, w45.x);
                    ffma2(acc[j][5], xs, w45.y);
                    ffma2(acc[j][6], xs, w67.x);
                    ffma2(acc[j][7], xs, w67.y);
                }
            }
        }
        __syncthreads();
        if (ch + 2 < NCHUNK)
            stage_x(xb, x_s + (ch & 1) * XBUF_FLOATS, ch + 2, tid);
    }
    __syncthreads();   /* x buffers retire; p_s overlay becomes safe */

    /* ---- write per-warp partials to smem (conflict-free, pad 20) ---- */
    #pragma unroll
    for (int j = 0; j < RPT; j++) {
        float* dst = p_s + (w * ROWS_PB + (l + 32 * j)) * LDP;
        #pragma unroll
        for (int i = 0; i < 4; i++) {
            float a  = __uint_as_float((unsigned int)(acc[j][2 * i] & 0xffffffffull));
            float bb = __uint_as_float((unsigned int)(acc[j][2 * i] >> 32));
            float c  = __uint_as_float((unsigned int)(acc[j][2 * i + 1] & 0xffffffffull));
            float d  = __uint_as_float((unsigned int)(acc[j][2 * i + 1] >> 32));
            *reinterpret_cast<float4*>(dst + 4 * i) = make_float4(a, bb, c, d);
        }
    }
    __syncthreads();

    /* ---- per-thread reduce + tanh + quantum encode ---- */
    const int row = base + tid;
    float s[16];
    #pragma unroll
    for (int i = 0; i < 4; i++) {
        float4 a0 = *reinterpret_cast<const float4*>(p_s + (0 * ROWS_PB + tid) * LDP + 4 * i);
        float4 a1 = *reinterpret_cast<const float4*>(p_s + (1 * ROWS_PB + tid) * LDP + 4 * i);
        float4 a2 = *reinterpret_cast<const float4*>(p_s + (2 * ROWS_PB + tid) * LDP + 4 * i);
        float4 a3 = *reinterpret_cast<const float4*>(p_s + (3 * ROWS_PB + tid) * LDP + 4 * i);
        float z0 = (a0.x + a1.x) + (a2.x + a3.x) + __ldg(&b[4 * i]);
        float z1 = (a0.y + a1.y) + (a2.y + a3.y) + __ldg(&b[4 * i + 1]);
        float z2 = (a0.z + a1.z) + (a2.z + a3.z) + __ldg(&b[4 * i + 2]);
        float z3 = (a0.w + a1.w) + (a2.w + a3.w) + __ldg(&b[4 * i + 3]);
        float e0 = __expf(2.0f * z0), e1 = __expf(2.0f * z1);
        float e2 = __expf(2.0f * z2), e3 = __expf(2.0f * z3);
        s[4 * i]     = __fdividef(e0 - 1.0f, e0 + 1.0f);
        s[4 * i + 1] = __fdividef(e1 - 1.0f, e1 + 1.0f);
        s[4 * i + 2] = __fdividef(e2 - 1.0f, e2 + 1.0f);
        s[4 * i + 3] = __fdividef(e3 - 1.0f, e3 + 1.0f);
    }
    float o[16];
    #pragma unroll
    for (int q = 0; q < NQ; q++) {
        float theta = s[2 * q]     + __ldg(&enc[q * 3 + 0]);
        float phi   = s[2 * q + 1] + __ldg(&enc[q * 3 + 1]);
        float sn, cs;
        __sincosf(0.5f * theta, &sn, &cs);
        o[2 * q]     = cs;
        o[2 * q + 1] = sn * __cosf(phi);
    }
    float4* op = reinterpret_cast<float4*>(out + (size_t)row * NF);
    #pragma unroll
    for (int i = 0; i < 4; i++)
        op[i] = make_float4(o[4 * i], o[4 * i + 1], o[4 * i + 2], o[4 * i + 3]);
}

extern "C" void kernel_launch(void* const* d_in, const int* in_sizes, int n_in,
                              void* d_out, int out_size) {
    const float* x   = (const float*)d_in[0];
    const float* W   = (const float*)d_in[1];
    const float* b   = (const float*)d_in[2];
    const float* enc = (const float*)d_in[3];
    float* out = (float*)d_out;

    cudaFuncSetAttribute(qadapter_fused,
                         cudaFuncAttributeMaxDynamicSharedMemorySize, SMEM_BYTES);
    qadapter_fused<<<ROWS_TOTAL / ROWS_PB, BLOCK, SMEM_BYTES>>>(x, W, b, enc, out);
}